// round 1
// baseline (speedup 1.0000x reference)
#include <cuda_runtime.h>
#include <cuda_bf16.h>

#define N_NODES 100000
#define N_EDGES 1000000
#define D_FEAT  64

// Scratch accumulator (device global — no allocations allowed)
__device__ float g_agg[N_NODES * D_FEAT];

// ---------------------------------------------------------------------------
// Kernel 1: initialize accumulator with X (this provides the "+ X[v]" self term)
// ---------------------------------------------------------------------------
__global__ void k_init(const float4* __restrict__ X4, float4* __restrict__ agg4, int n4) {
    int i = blockIdx.x * blockDim.x + threadIdx.x;
    if (i < n4) agg4[i] = X4[i];
}

// ---------------------------------------------------------------------------
// Kernel 2: edge scatter. 16 threads per edge, each handles one float4 chunk
// of the 64-float row, in BOTH directions. Uses vectorized red.global.add.v4.f32.
// ---------------------------------------------------------------------------
__device__ __forceinline__ void red_add_v4(float* addr, float4 v) {
    asm volatile("red.global.add.v4.f32 [%0], {%1, %2, %3, %4};"
                 :: "l"(addr), "f"(v.x), "f"(v.y), "f"(v.z), "f"(v.w)
                 : "memory");
}

__global__ void k_scatter(const float4* __restrict__ X4,
                          const int* __restrict__ ref_a,
                          const int* __restrict__ ref_b) {
    unsigned t = blockIdx.x * blockDim.x + threadIdx.x;   // 16M threads exactly
    unsigned e = t >> 4;         // edge id
    unsigned c = t & 15;         // float4 chunk within row (16 * float4 = 64 floats)
    if (e >= N_EDGES) return;
    int a = __ldg(&ref_a[e]);
    int b = __ldg(&ref_b[e]);
    const int F4 = D_FEAT / 4;   // 16
    float4 xb = __ldg(&X4[(size_t)b * F4 + c]);
    float4 xa = __ldg(&X4[(size_t)a * F4 + c]);
    red_add_v4(&g_agg[((size_t)a * F4 + c) * 4], xb);
    red_add_v4(&g_agg[((size_t)b * F4 + c) * 4], xa);
}

// ---------------------------------------------------------------------------
// Kernel 3: fused 2-layer MLP with ReLU.
//   out = relu(relu(agg @ Wh + bh) @ Wo + bo)
// One block = 64 rows. 256 threads (16x16), each computes a 4x4 micro-tile.
// Hidden tile is written back into the X-tile smem (never leaves the SM).
// Dynamic smem: Xs[64][65] + Wh[64][64] + Wo[64][64] = 49408 bytes.
// ---------------------------------------------------------------------------
#define XS_STRIDE 65

__global__ __launch_bounds__(256)
void k_mlp(const float* __restrict__ agg,
           const float* __restrict__ Wh_g, const float* __restrict__ bh_g,
           const float* __restrict__ Wo_g, const float* __restrict__ bo_g,
           float* __restrict__ out) {
    extern __shared__ float smem[];
    float* Xs = smem;                       // 64 * 65
    float* Wh = Xs + 64 * XS_STRIDE;        // 64 * 64
    float* Wo = Wh + 64 * 64;               // 64 * 64

    const int tid = threadIdx.x;
    const int ty = tid >> 4;      // 0..15 (row group)
    const int tx = tid & 15;      // 0..15 (col group)
    const int row0 = blockIdx.x * 64;

    // Load weights: 4096 floats each, 256 threads -> 4 float4 per thread each
    {
        const float4* Wh4 = (const float4*)Wh_g;
        const float4* Wo4 = (const float4*)Wo_g;
        float4* WhS = (float4*)Wh;
        float4* WoS = (float4*)Wo;
        #pragma unroll
        for (int i = 0; i < 4; i++) {
            WhS[tid + i * 256] = Wh4[tid + i * 256];
            WoS[tid + i * 256] = Wo4[tid + i * 256];
        }
    }

    // Load X tile: 64 rows x 16 float4 = 1024 float4, 4 per thread
    #pragma unroll
    for (int i = 0; i < 4; i++) {
        int idx = tid + i * 256;
        int r = idx >> 4;          // 0..63
        int c4 = idx & 15;         // 0..15
        int grow = row0 + r;
        float4 v = make_float4(0.f, 0.f, 0.f, 0.f);
        if (grow < N_NODES)
            v = __ldg(&((const float4*)agg)[(size_t)grow * 16 + c4]);
        float* dst = &Xs[r * XS_STRIDE + c4 * 4];
        dst[0] = v.x; dst[1] = v.y; dst[2] = v.z; dst[3] = v.w;
    }
    __syncthreads();

    // ---- Layer 1: hid = relu(Xs @ Wh + bh) ----
    float acc[4][4];
    {
        float b0 = bh_g[tx * 4 + 0], b1 = bh_g[tx * 4 + 1];
        float b2 = bh_g[tx * 4 + 2], b3 = bh_g[tx * 4 + 3];
        #pragma unroll
        for (int i = 0; i < 4; i++) {
            acc[i][0] = b0; acc[i][1] = b1; acc[i][2] = b2; acc[i][3] = b3;
        }
    }
    #pragma unroll 8
    for (int k = 0; k < 64; k++) {
        float a[4], w[4];
        #pragma unroll
        for (int i = 0; i < 4; i++) a[i] = Xs[(ty * 4 + i) * XS_STRIDE + k];
        #pragma unroll
        for (int j = 0; j < 4; j++) w[j] = Wh[k * 64 + tx * 4 + j];
        #pragma unroll
        for (int i = 0; i < 4; i++)
            #pragma unroll
            for (int j = 0; j < 4; j++)
                acc[i][j] = fmaf(a[i], w[j], acc[i][j]);
    }
    __syncthreads();   // everyone done reading Xs before we overwrite it with hid

    #pragma unroll
    for (int i = 0; i < 4; i++)
        #pragma unroll
        for (int j = 0; j < 4; j++)
            Xs[(ty * 4 + i) * XS_STRIDE + tx * 4 + j] = fmaxf(acc[i][j], 0.f);
    __syncthreads();

    // ---- Layer 2: out = relu(hid @ Wo + bo) ----
    {
        float b0 = bo_g[tx * 4 + 0], b1 = bo_g[tx * 4 + 1];
        float b2 = bo_g[tx * 4 + 2], b3 = bo_g[tx * 4 + 3];
        #pragma unroll
        for (int i = 0; i < 4; i++) {
            acc[i][0] = b0; acc[i][1] = b1; acc[i][2] = b2; acc[i][3] = b3;
        }
    }
    #pragma unroll 8
    for (int k = 0; k < 64; k++) {
        float a[4], w[4];
        #pragma unroll
        for (int i = 0; i < 4; i++) a[i] = Xs[(ty * 4 + i) * XS_STRIDE + k];
        #pragma unroll
        for (int j = 0; j < 4; j++) w[j] = Wo[k * 64 + tx * 4 + j];
        #pragma unroll
        for (int i = 0; i < 4; i++)
            #pragma unroll
            for (int j = 0; j < 4; j++)
                acc[i][j] = fmaf(a[i], w[j], acc[i][j]);
    }

    // Store 4x4 micro-tile (float4 per row — cols are 16B aligned)
    #pragma unroll
    for (int i = 0; i < 4; i++) {
        int grow = row0 + ty * 4 + i;
        if (grow < N_NODES) {
            float4 v = make_float4(fmaxf(acc[i][0], 0.f), fmaxf(acc[i][1], 0.f),
                                   fmaxf(acc[i][2], 0.f), fmaxf(acc[i][3], 0.f));
            ((float4*)out)[(size_t)grow * 16 + tx] = v;
        }
    }
}

// ---------------------------------------------------------------------------
// Launch
// Inputs: 0=X, 1=ref_a, 2=ref_b, 3=v_map(unused), 4=v_count(unused),
//         5=W_hidden, 6=b_hidden, 7=W_out, 8=b_out
// ---------------------------------------------------------------------------
extern "C" void kernel_launch(void* const* d_in, const int* in_sizes, int n_in,
                              void* d_out, int out_size) {
    const float* X   = (const float*)d_in[0];
    const int* ref_a = (const int*)d_in[1];
    const int* ref_b = (const int*)d_in[2];
    const float* Wh  = (const float*)d_in[5];
    const float* bh  = (const float*)d_in[6];
    const float* Wo  = (const float*)d_in[7];
    const float* bo  = (const float*)d_in[8];
    float* out = (float*)d_out;

    float* agg;
    cudaGetSymbolAddress((void**)&agg, g_agg);

    // 1) agg = X
    {
        int n4 = N_NODES * D_FEAT / 4;
        k_init<<<(n4 + 255) / 256, 256>>>((const float4*)X, (float4*)agg, n4);
    }

    // 2) edge scatter (both directions)
    {
        long long total = (long long)N_EDGES * 16;
        int blocks = (int)((total + 255) / 256);
        k_scatter<<<blocks, 256>>>((const float4*)X, ref_a, ref_b);
    }

    // 3) fused MLP
    {
        const int SMEM = (64 * XS_STRIDE + 64 * 64 + 64 * 64) * (int)sizeof(float); // 49408
        static bool attr_set = false;
        // setting the attribute is idempotent & deterministic; do it every call
        cudaFuncSetAttribute(k_mlp, cudaFuncAttributeMaxDynamicSharedMemorySize, SMEM);
        (void)attr_set;
        int blocks = (N_NODES + 63) / 64;
        k_mlp<<<blocks, 256, SMEM>>>(agg, Wh, bh, Wo, bo, out);
    }
}

// round 2
// speedup vs baseline: 1.1569x; 1.1569x over previous
#include <cuda_runtime.h>
#include <cuda_bf16.h>

#define N_NODES 100000
#define N_EDGES 1000000
#define D_FEAT  64

// Neighbor-sum accumulator. Zero-initialized at module load; k_mlp re-zeroes
// it after consuming, so every kernel_launch call sees zeros (graph-replay safe).
__device__ float g_agg[N_NODES * D_FEAT];

// ---------------------------------------------------------------------------
// Edge scatter: 16 threads per edge, one float4 chunk each, both directions.
// agg[v] accumulates ONLY the neighbor sums (self term added in k_mlp).
// ---------------------------------------------------------------------------
__device__ __forceinline__ void red_add_v4(float* addr, float4 v) {
    asm volatile("red.global.add.v4.f32 [%0], {%1, %2, %3, %4};"
                 :: "l"(addr), "f"(v.x), "f"(v.y), "f"(v.z), "f"(v.w)
                 : "memory");
}

__global__ void k_scatter(const float4* __restrict__ X4,
                          const int* __restrict__ ref_a,
                          const int* __restrict__ ref_b) {
    unsigned t = blockIdx.x * blockDim.x + threadIdx.x;
    unsigned e = t >> 4;
    unsigned c = t & 15;
    if (e >= N_EDGES) return;
    int a = __ldg(&ref_a[e]);
    int b = __ldg(&ref_b[e]);
    const int F4 = D_FEAT / 4;   // 16
    float4 xb = __ldg(&X4[(size_t)b * F4 + c]);
    float4 xa = __ldg(&X4[(size_t)a * F4 + c]);
    red_add_v4(&g_agg[((size_t)a * F4 + c) * 4], xb);
    red_add_v4(&g_agg[((size_t)b * F4 + c) * 4], xa);
}

// ---------------------------------------------------------------------------
// Fused TF32 tensor-core MLP:
//   out = relu(relu((X + agg) @ Wh + bh) @ Wo + bo)
// Block = 128 rows, 128 threads (4 warps), each warp owns a 32-row stripe.
// mma.sync.m16n8k8 tf32. Hidden never leaves smem. Also zeroes agg tile.
// ---------------------------------------------------------------------------
#define AS 68                      // smem row stride in words (68 % 32 == 4 -> conflict-free frags)
#define MLP_SMEM ((128 + 64 + 64) * AS * 4)   // As + W1 + W2 = 69632 bytes

__device__ __forceinline__ unsigned f2tf32(float f) {
    unsigned u;
    asm("cvt.rna.tf32.f32 %0, %1;" : "=r"(u) : "f"(f));
    return u;
}

__device__ __forceinline__ void mma_tf32(float* d, const unsigned* a,
                                         unsigned b0, unsigned b1) {
    asm volatile(
        "mma.sync.aligned.m16n8k8.row.col.f32.tf32.tf32.f32 "
        "{%0,%1,%2,%3}, {%4,%5,%6,%7}, {%8,%9}, {%0,%1,%2,%3};\n"
        : "+f"(d[0]), "+f"(d[1]), "+f"(d[2]), "+f"(d[3])
        : "r"(a[0]), "r"(a[1]), "r"(a[2]), "r"(a[3]), "r"(b0), "r"(b1));
}

__global__ __launch_bounds__(128)
void k_mlp(const float4* __restrict__ agg4, const float4* __restrict__ X4,
           const float* __restrict__ Wh_g, const float* __restrict__ bh,
           const float* __restrict__ Wo_g, const float* __restrict__ bo,
           float4* __restrict__ out4, float4* __restrict__ aggz) {
    extern __shared__ unsigned smem_u[];
    unsigned* As = smem_u;            // 128 x AS  (A tile / hidden / out staging)
    unsigned* W1 = As + 128 * AS;     // 64 x AS, layout [n*AS + k] (transposed)
    unsigned* W2 = W1 + 64 * AS;

    const int tid  = threadIdx.x;
    const int lane = tid & 31;
    const int warp = tid >> 5;
    const int g    = lane >> 2;       // groupID 0..7
    const int tig  = lane & 3;        // thread-in-group 0..3
    const int row0 = blockIdx.x * 128;
    const int rbase = warp * 32;

    // ---- Load weights transposed into smem as tf32: W[k][n] -> Ws[n*AS + k]
    {
        const float4* Wh4 = (const float4*)Wh_g;
        const float4* Wo4 = (const float4*)Wo_g;
        #pragma unroll
        for (int i = 0; i < 8; i++) {
            int idx4 = tid + i * 128;      // 0..1023
            int k  = idx4 >> 4;            // 0..63
            int n0 = (idx4 & 15) * 4;      // 0..60
            float4 wh = __ldg(&Wh4[idx4]);
            float4 wo = __ldg(&Wo4[idx4]);
            W1[(n0 + 0) * AS + k] = f2tf32(wh.x);
            W1[(n0 + 1) * AS + k] = f2tf32(wh.y);
            W1[(n0 + 2) * AS + k] = f2tf32(wh.z);
            W1[(n0 + 3) * AS + k] = f2tf32(wh.w);
            W2[(n0 + 0) * AS + k] = f2tf32(wo.x);
            W2[(n0 + 1) * AS + k] = f2tf32(wo.y);
            W2[(n0 + 2) * AS + k] = f2tf32(wo.z);
            W2[(n0 + 3) * AS + k] = f2tf32(wo.w);
        }
    }

    // ---- Load A tile: (X + agg) -> tf32
    #pragma unroll
    for (int i = 0; i < 16; i++) {
        int idx = tid + i * 128;          // 0..2047
        int r  = idx >> 4;                // 0..127
        int c4 = idx & 15;                // 0..15
        int grow = row0 + r;
        uint4 st = make_uint4(0u, 0u, 0u, 0u);
        if (grow < N_NODES) {
            float4 a = __ldg(&agg4[(size_t)grow * 16 + c4]);
            float4 x = __ldg(&X4[(size_t)grow * 16 + c4]);
            st.x = f2tf32(a.x + x.x);
            st.y = f2tf32(a.y + x.y);
            st.z = f2tf32(a.z + x.z);
            st.w = f2tf32(a.w + x.w);
        }
        *(uint4*)&As[r * AS + c4 * 4] = st;
    }
    __syncthreads();

    float acc[2][8][4];

    // ================= Layer 1: hid = relu(A @ Wh + bh) =================
    #pragma unroll
    for (int nt = 0; nt < 8; nt++) {
        int col = nt * 8 + 2 * tig;
        float blo = __ldg(&bh[col]);
        float bhi = __ldg(&bh[col + 1]);
        #pragma unroll
        for (int mt = 0; mt < 2; mt++) {
            acc[mt][nt][0] = blo; acc[mt][nt][1] = bhi;
            acc[mt][nt][2] = blo; acc[mt][nt][3] = bhi;
        }
    }
    #pragma unroll
    for (int ks = 0; ks < 8; ks++) {
        int kc = ks * 8;
        unsigned a[2][4];
        #pragma unroll
        for (int mt = 0; mt < 2; mt++) {
            int r = rbase + mt * 16 + g;
            a[mt][0] = As[r * AS + kc + tig];
            a[mt][1] = As[(r + 8) * AS + kc + tig];
            a[mt][2] = As[r * AS + kc + tig + 4];
            a[mt][3] = As[(r + 8) * AS + kc + tig + 4];
        }
        #pragma unroll
        for (int nt = 0; nt < 8; nt++) {
            unsigned b0 = W1[(nt * 8 + g) * AS + kc + tig];
            unsigned b1 = W1[(nt * 8 + g) * AS + kc + tig + 4];
            mma_tf32(acc[0][nt], a[0], b0, b1);
            mma_tf32(acc[1][nt], a[1], b0, b1);
        }
    }

    // Store hidden (relu, tf32) back into own 32-row stripe of As.
    __syncwarp();
    #pragma unroll
    for (int mt = 0; mt < 2; mt++) {
        int r = rbase + mt * 16 + g;
        #pragma unroll
        for (int nt = 0; nt < 8; nt++) {
            int c = nt * 8 + 2 * tig;
            As[r * AS + c]           = f2tf32(fmaxf(acc[mt][nt][0], 0.f));
            As[r * AS + c + 1]       = f2tf32(fmaxf(acc[mt][nt][1], 0.f));
            As[(r + 8) * AS + c]     = f2tf32(fmaxf(acc[mt][nt][2], 0.f));
            As[(r + 8) * AS + c + 1] = f2tf32(fmaxf(acc[mt][nt][3], 0.f));
        }
    }
    __syncwarp();

    // ================= Layer 2: out = relu(hid @ Wo + bo) =================
    #pragma unroll
    for (int nt = 0; nt < 8; nt++) {
        int col = nt * 8 + 2 * tig;
        float blo = __ldg(&bo[col]);
        float bhi = __ldg(&bo[col + 1]);
        #pragma unroll
        for (int mt = 0; mt < 2; mt++) {
            acc[mt][nt][0] = blo; acc[mt][nt][1] = bhi;
            acc[mt][nt][2] = blo; acc[mt][nt][3] = bhi;
        }
    }
    #pragma unroll
    for (int ks = 0; ks < 8; ks++) {
        int kc = ks * 8;
        unsigned a[2][4];
        #pragma unroll
        for (int mt = 0; mt < 2; mt++) {
            int r = rbase + mt * 16 + g;
            a[mt][0] = As[r * AS + kc + tig];
            a[mt][1] = As[(r + 8) * AS + kc + tig];
            a[mt][2] = As[r * AS + kc + tig + 4];
            a[mt][3] = As[(r + 8) * AS + kc + tig + 4];
        }
        #pragma unroll
        for (int nt = 0; nt < 8; nt++) {
            unsigned b0 = W2[(nt * 8 + g) * AS + kc + tig];
            unsigned b1 = W2[(nt * 8 + g) * AS + kc + tig + 4];
            mma_tf32(acc[0][nt], a[0], b0, b1);
            mma_tf32(acc[1][nt], a[1], b0, b1);
        }
    }

    // Stage fp32 output into As stripe (overwrite hidden).
    __syncwarp();
    #pragma unroll
    for (int mt = 0; mt < 2; mt++) {
        int r = rbase + mt * 16 + g;
        #pragma unroll
        for (int nt = 0; nt < 8; nt++) {
            int c = nt * 8 + 2 * tig;
            As[r * AS + c]           = __float_as_uint(fmaxf(acc[mt][nt][0], 0.f));
            As[r * AS + c + 1]       = __float_as_uint(fmaxf(acc[mt][nt][1], 0.f));
            As[(r + 8) * AS + c]     = __float_as_uint(fmaxf(acc[mt][nt][2], 0.f));
            As[(r + 8) * AS + c + 1] = __float_as_uint(fmaxf(acc[mt][nt][3], 0.f));
        }
    }
    __syncthreads();

    // Coalesced float4 store of out, and zero agg tile for the next run.
    const float4 z4 = make_float4(0.f, 0.f, 0.f, 0.f);
    #pragma unroll
    for (int i = 0; i < 16; i++) {
        int idx = tid + i * 128;
        int r  = idx >> 4;
        int c4 = idx & 15;
        int grow = row0 + r;
        if (grow < N_NODES) {
            uint4 v = *(uint4*)&As[r * AS + c4 * 4];
            out4[(size_t)grow * 16 + c4] = make_float4(
                __uint_as_float(v.x), __uint_as_float(v.y),
                __uint_as_float(v.z), __uint_as_float(v.w));
            aggz[(size_t)grow * 16 + c4] = z4;
        }
    }
}

// ---------------------------------------------------------------------------
// Inputs: 0=X, 1=ref_a, 2=ref_b, 3=v_map(unused), 4=v_count(unused),
//         5=W_hidden, 6=b_hidden, 7=W_out, 8=b_out
// ---------------------------------------------------------------------------
extern "C" void kernel_launch(void* const* d_in, const int* in_sizes, int n_in,
                              void* d_out, int out_size) {
    const float* X   = (const float*)d_in[0];
    const int* ref_a = (const int*)d_in[1];
    const int* ref_b = (const int*)d_in[2];
    const float* Wh  = (const float*)d_in[5];
    const float* bh  = (const float*)d_in[6];
    const float* Wo  = (const float*)d_in[7];
    const float* bo  = (const float*)d_in[8];
    float* out = (float*)d_out;

    float* agg;
    cudaGetSymbolAddress((void**)&agg, g_agg);

    // 1) edge scatter into zeroed agg (agg zero-invariant maintained by k_mlp)
    {
        long long total = (long long)N_EDGES * 16;
        int blocks = (int)((total + 255) / 256);
        k_scatter<<<blocks, 256>>>((const float4*)X, ref_a, ref_b);
    }

    // 2) fused TF32 MLP (adds X, consumes agg, re-zeroes agg)
    {
        cudaFuncSetAttribute(k_mlp, cudaFuncAttributeMaxDynamicSharedMemorySize,
                             MLP_SMEM);
        int blocks = (N_NODES + 127) / 128;
        k_mlp<<<blocks, 128, MLP_SMEM>>>(
            (const float4*)agg, (const float4*)X, Wh, bh, Wo, bo,
            (float4*)out, (float4*)agg);
    }
}